// round 5
// baseline (speedup 1.0000x reference)
#include <cuda_runtime.h>
#include <math.h>

#define H 1024
#define E 512
#define A 512
#define L 512
#define V 50257
#define NSLICE 16

// K1 role layout (blocks of 256 threads, warp-per-row)
#define SCORE_BLKS 64     // 512 attn rows
#define GHH_BLKS   512    // 4096 gates_hh rows
#define COMBP_BLKS 128    // 1024 comb emb/av partial rows
#define K1_REAL    (SCORE_BLKS + GHH_BLKS + COMBP_BLKS)

#define APPLY_REAL 16     // attn apply slices
#define COMB2_REAL 128    // 1024 comb attn-col rows
#define GIH_REAL   512    // 4096 gates_ih rows

// prefetch blocks (128 KB each) for out_W, evict_last
#define PF2 128           // out_W[0:16MB)
#define PF3 128           // out_W[16MB:32MB)
#define PF4 256           // out_W[32MB:64MB)

// ---------------- scratch (device globals) ----------------------------------
__device__ __align__(16) float g_scores[L];
__device__ __align__(16) float g_part[NSLICE * H];
__device__ __align__(16) float g_ghh[4 * H];     // W_hh @ h0 partial
__device__ __align__(16) float g_xpart[H];       // comb emb/av partial
__device__ __align__(16) float g_x[H];
__device__ __align__(16) float g_gates[4 * H];
__device__ __align__(16) float g_h[H];
__device__ unsigned g_sem;

__device__ __forceinline__ float warp_sum(float v) {
#pragma unroll
    for (int o = 16; o > 0; o >>= 1) v += __shfl_down_sync(0xffffffffu, v, o);
    return v;
}

__device__ __forceinline__ void pf_chunk_last(const char* base, int blk) {
    const char* p = base + (size_t)blk * 131072 + (size_t)threadIdx.x * 128;
#pragma unroll
    for (int i = 0; i < 4; i++)
        asm volatile("prefetch.global.L2::evict_last [%0];" :: "l"(p + i * 32768));
}

// ---------------- K1: all t=0-independent streams ---------------------------
__global__ __launch_bounds__(256) void k1_indep(
        const int* __restrict__ word, const float* __restrict__ emb,
        const float* __restrict__ h0, const float* __restrict__ av,
        const float* __restrict__ attn_W, const float* __restrict__ attn_b,
        const float* __restrict__ W_hh, const float* __restrict__ comb_W) {
    __shared__ float sc[E + H];   // biggest role buffer (1536 floats)
    int t = threadIdx.x, lane = t & 31, w = t >> 5;
    int b = blockIdx.x;

    if (b < SCORE_BLKS) {
        // ---- attn scores: row = b*8 + w, dot over [emb; h0] (1536) ----
        long wrow = (long)word[0] * E;
#pragma unroll
        for (int i = t; i < E + H; i += 256)
            sc[i] = (i < E) ? emb[wrow + i] : h0[i - E];
        __syncthreads();
        int row = b * 8 + w;
        const float4* wr = reinterpret_cast<const float4*>(attn_W) + (size_t)row * 384;
        const float4* c4 = reinterpret_cast<const float4*>(sc);
        float s = 0.f;
#pragma unroll
        for (int i = 0; i < 12; i++) {
            float4 a = __ldcs(&wr[lane + 32 * i]);
            float4 c = c4[lane + 32 * i];
            s += a.x * c.x + a.y * c.y + a.z * c.z + a.w * c.w;
        }
        s = warp_sum(s);
        if (lane == 0) g_scores[row] = s + attn_b[row];
    } else if (b < SCORE_BLKS + GHH_BLKS) {
        // ---- gates_hh: row = (b-64)*8 + w, dot(W_hh[row], h0) ----
#pragma unroll
        for (int i = t; i < H; i += 256) sc[i] = h0[i];
        __syncthreads();
        int row = (b - SCORE_BLKS) * 8 + w;
        const float4* wr = reinterpret_cast<const float4*>(W_hh) + (size_t)row * 256;
        const float4* c4 = reinterpret_cast<const float4*>(sc);
        float s = 0.f;
#pragma unroll
        for (int i = 0; i < 8; i++) {
            float4 a = __ldcs(&wr[lane + 32 * i]);
            float4 c = c4[lane + 32 * i];
            s += a.x * c.x + a.y * c.y + a.z * c.z + a.w * c.w;
        }
        s = warp_sum(s);
        if (lane == 0) g_ghh[row] = s;
    } else {
        // ---- comb partial over emb cols [0,512) + av cols [1536,2048) ----
        long wrow = (long)word[0] * E;
#pragma unroll
        for (int i = t; i < E; i += 256) { sc[i] = emb[wrow + i]; sc[E + i] = av[i]; }
        __syncthreads();
        int row = (b - SCORE_BLKS - GHH_BLKS) * 8 + w;
        const float4* wr = reinterpret_cast<const float4*>(comb_W) + (size_t)row * 512;
        const float4* c4 = reinterpret_cast<const float4*>(sc);
        float s = 0.f;
#pragma unroll
        for (int i = 0; i < 4; i++) {
            float4 a = __ldcs(&wr[lane + 32 * i]);            // emb cols
            float4 c = c4[lane + 32 * i];
            s += a.x * c.x + a.y * c.y + a.z * c.z + a.w * c.w;
            float4 a2 = __ldcs(&wr[384 + lane + 32 * i]);     // av cols
            float4 c2 = c4[128 + lane + 32 * i];
            s += a2.x * c2.x + a2.y * c2.y + a2.z * c2.z + a2.w * c2.w;
        }
        s = warp_sum(s);
        if (lane == 0) g_xpart[row] = s;
    }
}

// ---------------- K2: softmax + attn apply partials (+ pf out_W[0:16M)) -----
__global__ __launch_bounds__(256) void k2_apply(
        const float* __restrict__ enc, float* __restrict__ d_attn_out,
        const float* __restrict__ out_W) {
    if (blockIdx.x >= APPLY_REAL) {
        pf_chunk_last((const char*)out_W, blockIdx.x - APPLY_REAL);
        return;
    }
    __shared__ float sred[8];
    __shared__ float sw[L];
    __shared__ float sbc;
    int t = threadIdx.x, lane = t & 31, wid = t >> 5;

    float v0 = g_scores[t], v1 = g_scores[t + 256];
    float m = fmaxf(v0, v1);
#pragma unroll
    for (int o = 16; o > 0; o >>= 1) m = fmaxf(m, __shfl_xor_sync(0xffffffffu, m, o));
    if (lane == 0) sred[wid] = m;
    __syncthreads();
    if (t == 0) {
        float mm = sred[0];
#pragma unroll
        for (int i = 1; i < 8; i++) mm = fmaxf(mm, sred[i]);
        sbc = mm;
    }
    __syncthreads();
    float bmax = sbc;
    float e0 = expf(v0 - bmax), e1 = expf(v1 - bmax);
    float su = e0 + e1;
#pragma unroll
    for (int o = 16; o > 0; o >>= 1) su += __shfl_xor_sync(0xffffffffu, su, o);
    __syncthreads();
    if (lane == 0) sred[wid] = su;
    __syncthreads();
    if (t == 0) {
        float ss = 0.f;
#pragma unroll
        for (int i = 0; i < 8; i++) ss += sred[i];
        sbc = ss;
    }
    __syncthreads();
    float inv = 1.0f / sbc;
    float w0 = e0 * inv, w1 = e1 * inv;
    sw[t] = w0; sw[t + 256] = w1;
    if (blockIdx.x == 0) { d_attn_out[t] = w0; d_attn_out[t + 256] = w1; }
    __syncthreads();

    // slice of 32 encoder rows, all 256 f4 columns
    int l0 = blockIdx.x * (L / NSLICE);
    const float4* e4 = reinterpret_cast<const float4*>(enc);
    float4 acc = make_float4(0.f, 0.f, 0.f, 0.f);
#pragma unroll
    for (int l = 0; l < L / NSLICE; l++) {
        float wk = sw[l0 + l];
        float4 x = __ldcs(&e4[(size_t)(l0 + l) * 256 + t]);
        acc.x += wk * x.x; acc.y += wk * x.y; acc.z += wk * x.z; acc.w += wk * x.w;
    }
    reinterpret_cast<float4*>(g_part)[blockIdx.x * 256 + t] = acc;
}

// ---------------- K3: comb attn columns + finish x (+ pf out_W[16:32M)) -----
__global__ __launch_bounds__(256) void k3_comb(
        const float* __restrict__ comb_W, const float* __restrict__ comb_b,
        const float* __restrict__ out_W) {
    if (blockIdx.x >= COMB2_REAL) {
        pf_chunk_last((const char*)out_W + (size_t)PF2 * 131072,
                      blockIdx.x - COMB2_REAL);
        return;
    }
    __shared__ float sat[H];
    int t = threadIdx.x, lane = t & 31, w = t >> 5;
#pragma unroll
    for (int i = t; i < H; i += 256) {
        float s = 0.f;
#pragma unroll
        for (int p = 0; p < NSLICE; p++) s += g_part[p * H + i];
        sat[i] = s;
    }
    __syncthreads();
    int row = blockIdx.x * 8 + w;
    // attn columns of comb_W: f4 indices [128, 384)
    const float4* wr = reinterpret_cast<const float4*>(comb_W) + (size_t)row * 512 + 128;
    const float4* c4 = reinterpret_cast<const float4*>(sat);
    float s = 0.f;
#pragma unroll
    for (int i = 0; i < 8; i++) {
        float4 a = __ldcs(&wr[lane + 32 * i]);
        float4 c = c4[lane + 32 * i];
        s += a.x * c.x + a.y * c.y + a.z * c.z + a.w * c.w;
    }
    s = warp_sum(s);
    if (lane == 0) g_x[row] = fmaxf(s + g_xpart[row] + comb_b[row], 0.f);
}

// ---------------- K4: gates_ih + fused LSTM (last block) (+ pf) --------------
__global__ __launch_bounds__(256) void k4_gates(
        const float* __restrict__ W_ih, const float* __restrict__ b_ih,
        const float* __restrict__ b_hh, const float* __restrict__ c0,
        float* __restrict__ d_h, float* __restrict__ d_c,
        const float* __restrict__ out_W) {
    if (blockIdx.x >= GIH_REAL) {
        pf_chunk_last((const char*)out_W + (size_t)(PF2 + PF3) * 131072,
                      blockIdx.x - GIH_REAL);
        return;
    }
    __shared__ float sx[H];
    __shared__ bool s_last;
    int t = threadIdx.x, lane = t & 31, w = t >> 5;
#pragma unroll
    for (int i = t; i < H; i += 256) sx[i] = g_x[i];
    __syncthreads();
    int row = blockIdx.x * 8 + w;
    const float4* wr = reinterpret_cast<const float4*>(W_ih) + (size_t)row * 256;
    const float4* c4 = reinterpret_cast<const float4*>(sx);
    float s = 0.f;
#pragma unroll
    for (int i = 0; i < 8; i++) {
        float4 a = __ldcs(&wr[lane + 32 * i]);
        float4 c = c4[lane + 32 * i];
        s += a.x * c.x + a.y * c.y + a.z * c.z + a.w * c.w;
    }
    s = warp_sum(s);
    if (lane == 0) g_gates[row] = s + g_ghh[row] + b_ih[row] + b_hh[row];
    __syncthreads();

    // last-block LSTM
    if (t == 0) {
        __threadfence();
        unsigned old = atomicAdd(&g_sem, 1u);
        s_last = (old == GIH_REAL - 1);
        if (s_last) g_sem = 0;            // reset for next graph replay
    }
    __syncthreads();
    if (s_last) {
        __threadfence();
#pragma unroll
        for (int r = 0; r < 4; r++) {
            int k = t + 256 * r;
            float gi = g_gates[k];
            float gf = g_gates[H + k];
            float gg = g_gates[2 * H + k];
            float go = g_gates[3 * H + k];
            float si = 1.f / (1.f + expf(-gi));
            float sf = 1.f / (1.f + expf(-gf));
            float so = 1.f / (1.f + expf(-go));
            float cn = sf * c0[k] + si * tanhf(gg);
            float hn = so * tanhf(cn);
            g_h[k] = hn;
            d_h[k] = hn;
            d_c[k] = cn;
        }
    }
}

// ---------------- K5: logits (50257 x 1024), 2 rows per warp ----------------
__global__ __launch_bounds__(256) void k_logits(
        const float* __restrict__ out_W, const float* __restrict__ out_b,
        float* __restrict__ logits) {
    __shared__ float4 sh[H / 4];
    int t = threadIdx.x, lane = t & 31, w = t >> 5;
    sh[t] = reinterpret_cast<const float4*>(g_h)[t];
    __syncthreads();
    int r0 = blockIdx.x * 16 + 2 * w;
    int r1 = r0 + 1;
    int r0c = r0 < V ? r0 : V - 1;
    int r1c = r1 < V ? r1 : V - 1;
    const float4* wr0 = reinterpret_cast<const float4*>(out_W) + (size_t)r0c * 256;
    const float4* wr1 = reinterpret_cast<const float4*>(out_W) + (size_t)r1c * 256;
    float s0 = 0.f, s1 = 0.f;
#pragma unroll
    for (int i = 0; i < 8; i++) {
        float4 a = __ldcs(&wr0[lane + 32 * i]);
        float4 b = __ldcs(&wr1[lane + 32 * i]);
        float4 h = sh[lane + 32 * i];
        s0 += a.x * h.x + a.y * h.y + a.z * h.z + a.w * h.w;
        s1 += b.x * h.x + b.y * h.y + b.z * h.z + b.w * h.w;
    }
    s0 = warp_sum(s0);
    s1 = warp_sum(s1);
    if (lane == 0) {
        if (r0 < V) logits[r0] = s0 + out_b[r0];
        if (r1 < V) logits[r1] = s1 + out_b[r1];
    }
}

// ---------------- launch ----------------------------------------------------
extern "C" void kernel_launch(void* const* d_in, const int* in_sizes, int n_in,
                              void* d_out, int out_size) {
    (void)out_size;
    const int* word = (const int*)d_in[0];
    int k = (n_in >= 2 && in_sizes[1] == 1) ? 2 : 1;
    const float* av_emb  = (const float*)d_in[k + 0];
    const float* h0      = (const float*)d_in[k + 1];
    const float* c0      = (const float*)d_in[k + 2];
    const float* enc_out = (const float*)d_in[k + 3];
    const float* emb     = (const float*)d_in[k + 4];
    const float* attn_W  = (const float*)d_in[k + 5];
    const float* attn_b  = (const float*)d_in[k + 6];
    const float* comb_W  = (const float*)d_in[k + 7];
    const float* comb_b  = (const float*)d_in[k + 8];
    const float* W_ih    = (const float*)d_in[k + 9];
    const float* W_hh    = (const float*)d_in[k + 10];
    const float* b_ih    = (const float*)d_in[k + 11];
    const float* b_hh    = (const float*)d_in[k + 12];
    const float* out_W   = (const float*)d_in[k + 13];
    const float* out_b   = (const float*)d_in[k + 14];

    float* out = (float*)d_out;
    float* o_logits = out;              // [V]
    float* o_h      = out + V;          // [H]
    float* o_c      = out + V + H;      // [H]
    float* o_attn   = out + V + 2 * H;  // [L]

    k1_indep<<<K1_REAL, 256>>>(word, emb, h0, av_emb, attn_W, attn_b, W_hh, comb_W);
    k2_apply<<<APPLY_REAL + PF2, 256>>>(enc_out, o_attn, out_W);
    k3_comb<<<COMB2_REAL + PF3, 256>>>(comb_W, comb_b, out_W);
    k4_gates<<<GIH_REAL + PF4, 256>>>(W_ih, b_ih, b_hh, c0, o_h, o_c, out_W);
    k_logits<<<(V + 15) / 16, 256>>>(out_W, out_b, o_logits);
}